// round 11
// baseline (speedup 1.0000x reference)
#include <cuda_runtime.h>
#include <math.h>

#define BATCH 1024
#define INPUT_SIZE 512
#define HIDDEN 1024
#define N_QP 64
#define M_QP 128
#define QP_ITER 50
#define N_P 2080          // 64*65/2
#define N_HMAT 8192       // 128*64
#define N_OUT 10464       // 2080 + 64 + 8192 + 128
#define HOFF 2144         // N_P + N_QP

__device__ __align__(16) float g_h1[BATCH * HIDDEN];
__device__ __align__(16) float g_h2[BATCH * HIDDEN];
__device__ __align__(16) float g_out3[BATCH * N_OUT];
__device__ __align__(16) float g_minv[BATCH * N_QP * N_QP];
__device__ __align__(16) float g_tau[BATCH];

// ---------------------------------------------------------------------------
// Tiled fp32 SGEMM with fused bias (+ optional ReLU) — unchanged (fp32 peak)
// ---------------------------------------------------------------------------
template <bool RELU>
__global__ __launch_bounds__(256)
void sgemm_bias(const float* __restrict__ A, const float* __restrict__ B,
                const float* __restrict__ bias, float* __restrict__ C,
                int M, int N, int K)
{
    __shared__ float As[16 * 65];
    __shared__ float Bs[16 * 64];

    const int tid = threadIdx.x;
    const int tx = tid & 15;
    const int ty = tid >> 4;
    const int m0 = blockIdx.y * 64;
    const int n0 = blockIdx.x * 64;

    const int aRow = tid >> 2;
    const int aC4  = tid & 3;
    const int bRow = tid >> 4;
    const int bC4  = tid & 15;

    float acc[4][4] = {};

    for (int k0 = 0; k0 < K; k0 += 16) {
        float4 av = *(const float4*)&A[(size_t)(m0 + aRow) * K + k0 + aC4 * 4];
        int bn = n0 + bC4 * 4;
        float4 bv = make_float4(0.f, 0.f, 0.f, 0.f);
        if (bn < N) bv = *(const float4*)&B[(size_t)(k0 + bRow) * N + bn];

        __syncthreads();
        As[(aC4 * 4 + 0) * 65 + aRow] = av.x;
        As[(aC4 * 4 + 1) * 65 + aRow] = av.y;
        As[(aC4 * 4 + 2) * 65 + aRow] = av.z;
        As[(aC4 * 4 + 3) * 65 + aRow] = av.w;
        *(float4*)&Bs[bRow * 64 + bC4 * 4] = bv;
        __syncthreads();

        #pragma unroll
        for (int k = 0; k < 16; ++k) {
            float4 bb = *(const float4*)&Bs[k * 64 + tx * 4];
            float a0 = As[k * 65 + ty * 4 + 0];
            float a1 = As[k * 65 + ty * 4 + 1];
            float a2 = As[k * 65 + ty * 4 + 2];
            float a3 = As[k * 65 + ty * 4 + 3];
            acc[0][0] = fmaf(a0, bb.x, acc[0][0]);
            acc[0][1] = fmaf(a0, bb.y, acc[0][1]);
            acc[0][2] = fmaf(a0, bb.z, acc[0][2]);
            acc[0][3] = fmaf(a0, bb.w, acc[0][3]);
            acc[1][0] = fmaf(a1, bb.x, acc[1][0]);
            acc[1][1] = fmaf(a1, bb.y, acc[1][1]);
            acc[1][2] = fmaf(a1, bb.z, acc[1][2]);
            acc[1][3] = fmaf(a1, bb.w, acc[1][3]);
            acc[2][0] = fmaf(a2, bb.x, acc[2][0]);
            acc[2][1] = fmaf(a2, bb.y, acc[2][1]);
            acc[2][2] = fmaf(a2, bb.z, acc[2][2]);
            acc[2][3] = fmaf(a2, bb.w, acc[2][3]);
            acc[3][0] = fmaf(a3, bb.x, acc[3][0]);
            acc[3][1] = fmaf(a3, bb.y, acc[3][1]);
            acc[3][2] = fmaf(a3, bb.z, acc[3][2]);
            acc[3][3] = fmaf(a3, bb.w, acc[3][3]);
        }
    }

    #pragma unroll
    for (int ii = 0; ii < 4; ++ii) {
        int m = m0 + ty * 4 + ii;
        #pragma unroll
        for (int jj = 0; jj < 4; ++jj) {
            int n = n0 + tx * 4 + jj;
            if (n < N) {
                float v = acc[ii][jj] + bias[n];
                if (RELU) v = fmaxf(v, 0.f);
                C[(size_t)m * N + n] = v;
            }
        }
    }
}

// ---------------------------------------------------------------------------
// Kernel A — setup (round-4 solver minus QP loop). 256 threads / item.
// Computes tau and Minv = (I + tau*P)^-1, writes both to gmem scratch.
//   rH[32]: thread t holds H[r][32h+k], r=t>>1, h=t&1
//   rM[16]: thread t holds M[c][16g+j], c=t>>2, g=t&3
// ---------------------------------------------------------------------------
__device__ __forceinline__ float sel16(const float* r, int kj) {
    float v = r[0];
    #pragma unroll
    for (int j = 1; j < 16; ++j) v = (j == kj) ? r[j] : v;
    return v;
}

#define SETUP_SMEM_FLOATS (128 * 65 + 64 * 65)

__global__ __launch_bounds__(256, 2)
void setup_kernel(const float* __restrict__ out3,
                  float* __restrict__ minv_out, float* __restrict__ tau_out)
{
    extern __shared__ __align__(16) float smdyn[];
    float* sH = smdyn;              // 128*65  (H)
    float* sQ = sH + 128 * 65;      // 64*65   (L)

    __shared__ __align__(16) float spiv[2 * 64];
    __shared__ __align__(16) float sq[64];
    __shared__ __align__(16) float sv[64];
    __shared__ __align__(16) float sw[128];
    __shared__ float spart[8];
    __shared__ float s_scal, s_tau;

    const int t    = threadIdx.x;
    const int lane = t & 31;
    const int warp = t >> 5;
    const int r    = t >> 1;   // 0..127
    const int h    = t & 1;
    const int c    = t >> 2;   // 0..63
    const int g    = t & 3;

    const float* row = out3 + (size_t)blockIdx.x * N_OUT;
    const unsigned FULL = 0xffffffffu;

    // ---- Load H into registers (coalesced) and smem ----
    float rH[32];
    {
        const float4* base = (const float4*)(row + HOFF + r * 64 + 32 * h);
        #pragma unroll
        for (int k4 = 0; k4 < 8; ++k4) {
            float4 v = base[k4];
            rH[4*k4+0] = v.x; rH[4*k4+1] = v.y; rH[4*k4+2] = v.z; rH[4*k4+3] = v.w;
            sH[r * 65 + 32 * h + 4 * k4 + 0] = v.x;
            sH[r * 65 + 32 * h + 4 * k4 + 1] = v.y;
            sH[r * 65 + 32 * h + 4 * k4 + 2] = v.z;
            sH[r * 65 + 32 * h + 4 * k4 + 3] = v.w;
        }
    }
    if (t < 64)  sq[t] = row[N_P + t];
    if (t < 64)  sv[t] = 0.125f;
    __syncthreads();

    // ================= Power iteration =================
    for (int pit = 0; pit < 10; ++pit) {
        {
            const float4* x4 = (const float4*)(sv + 32 * h);
            float a0=0.f,a1=0.f,a2=0.f,a3=0.f;
            #pragma unroll
            for (int k4 = 0; k4 < 8; ++k4) {
                float4 xv = x4[k4];
                a0 = fmaf(rH[4*k4+0], xv.x, a0);
                a1 = fmaf(rH[4*k4+1], xv.y, a1);
                a2 = fmaf(rH[4*k4+2], xv.z, a2);
                a3 = fmaf(rH[4*k4+3], xv.w, a3);
            }
            float s = (a0 + a1) + (a2 + a3);
            s += __shfl_xor_sync(FULL, s, 1);
            if (h == 0) sw[r] = s;
        }
        __syncthreads();
        {
            float a0=0.f,a1=0.f,a2=0.f,a3=0.f;
            #pragma unroll
            for (int j0 = 0; j0 < 32; j0 += 4) {
                int jj0 = (j0 + 0 + 8 * g) & 31;
                int jj1 = (j0 + 1 + 8 * g) & 31;
                int jj2 = (j0 + 2 + 8 * g) & 31;
                int jj3 = (j0 + 3 + 8 * g) & 31;
                a0 = fmaf(sH[(32*g + jj0) * 65 + c], sw[32*g + jj0], a0);
                a1 = fmaf(sH[(32*g + jj1) * 65 + c], sw[32*g + jj1], a1);
                a2 = fmaf(sH[(32*g + jj2) * 65 + c], sw[32*g + jj2], a2);
                a3 = fmaf(sH[(32*g + jj3) * 65 + c], sw[32*g + jj3], a3);
            }
            float p = (a0 + a1) + (a2 + a3);
            p += __shfl_xor_sync(FULL, p, 1);
            p += __shfl_xor_sync(FULL, p, 2);
            float pp = (g == 0) ? p * p : 0.f;
            #pragma unroll
            for (int off = 16; off >= 1; off >>= 1)
                pp += __shfl_xor_sync(FULL, pp, off);
            if (lane == 0) spart[warp] = pp;
            __syncthreads();
            if (t == 0) {
                float sm = 0.f;
                #pragma unroll
                for (int i = 0; i < 8; ++i) sm += spart[i];
                s_scal = sqrtf(sm) + 1e-12f;
            }
            __syncthreads();
            if (g == 0) sv[c] = p / s_scal;
        }
        __syncthreads();
    }

    // ---- tau = 0.9/(||H v|| + 1e-6) ----
    {
        const float4* x4 = (const float4*)(sv + 32 * h);
        float a0=0.f,a1=0.f,a2=0.f,a3=0.f;
        #pragma unroll
        for (int k4 = 0; k4 < 8; ++k4) {
            float4 xv = x4[k4];
            a0 = fmaf(rH[4*k4+0], xv.x, a0);
            a1 = fmaf(rH[4*k4+1], xv.y, a1);
            a2 = fmaf(rH[4*k4+2], xv.z, a2);
            a3 = fmaf(rH[4*k4+3], xv.w, a3);
        }
        float s = (a0 + a1) + (a2 + a3);
        s += __shfl_xor_sync(FULL, s, 1);
        float pp = (h == 0) ? s * s : 0.f;
        #pragma unroll
        for (int off = 16; off >= 1; off >>= 1)
            pp += __shfl_xor_sync(FULL, pp, off);
        if (lane == 0) spart[warp] = pp;
        __syncthreads();
        if (t == 0) {
            float sm = 0.f;
            #pragma unroll
            for (int i = 0; i < 8; ++i) sm += spart[i];
            s_tau = 0.9f / (sqrtf(sm) + 1e-6f);
        }
    }

    // ================= Build L =================
    for (int idx = t; idx < 64 * 65; idx += 256) sQ[idx] = 0.f;
    __syncthreads();
    for (int idx = t; idx < N_P; idx += 256) {
        float p = row[idx];
        int rr = (int)((sqrtf(8.f * (float)idx + 1.f) - 1.f) * 0.5f);
        while ((rr * (rr + 1)) / 2 > idx) --rr;
        while (((rr + 1) * (rr + 2)) / 2 <= idx) ++rr;
        int cc = idx - (rr * (rr + 1)) / 2;
        float val;
        if (cc == rr) {
            float sp = fmaxf(p, 0.f) + log1pf(expf(-fabsf(p)));
            val = 0.1f + sp;
        } else {
            val = p;
        }
        sQ[rr * 65 + cc] = val;
    }
    __syncthreads();
    const float tau = s_tau;

    // ================= rM = I + tau * (L L^T) slice ==========
    float rM[16];
    #pragma unroll
    for (int j = 0; j < 16; ++j) rM[j] = 0.f;
    for (int k = 0; k < 64; ++k) {
        float a = sQ[c * 65 + k];
        #pragma unroll
        for (int j = 0; j < 16; ++j)
            rM[j] = fmaf(a, sQ[(16 * g + j) * 65 + k], rM[j]);
    }
    #pragma unroll
    for (int j = 0; j < 16; ++j) {
        int col = 16 * g + j;
        rM[j] = tau * rM[j] + ((col == c) ? 1.f : 0.f);
    }
    __syncthreads();

    // ================= Gauss-Jordan inverse ============
    for (int k = 0; k < 64; ++k) {
        const int kc = k >> 4, kj = k & 15;
        float* buf = spiv + (k & 1) * 64;
        float praw = __shfl_sync(FULL, sel16(rM, kj), (lane & ~3) | kc);
        if (c == k) {
            float pinv = 1.f / praw;
            #pragma unroll
            for (int j = 0; j < 16; ++j) {
                bool isk = (g == kc) && (j == kj);
                rM[j] = isk ? pinv : rM[j] * pinv;
            }
            *(float4*)&buf[16*g +  0] = make_float4(rM[0],  rM[1],  rM[2],  rM[3]);
            *(float4*)&buf[16*g +  4] = make_float4(rM[4],  rM[5],  rM[6],  rM[7]);
            *(float4*)&buf[16*g +  8] = make_float4(rM[8],  rM[9],  rM[10], rM[11]);
            *(float4*)&buf[16*g + 12] = make_float4(rM[12], rM[13], rM[14], rM[15]);
        }
        __syncthreads();
        if (c != k) {
            const float f = praw;
            float4 p0 = *(const float4*)&buf[16*g +  0];
            float4 p1 = *(const float4*)&buf[16*g +  4];
            float4 p2 = *(const float4*)&buf[16*g +  8];
            float4 p3 = *(const float4*)&buf[16*g + 12];
            float pv[16] = {p0.x,p0.y,p0.z,p0.w, p1.x,p1.y,p1.z,p1.w,
                            p2.x,p2.y,p2.z,p2.w, p3.x,p3.y,p3.z,p3.w};
            #pragma unroll
            for (int j = 0; j < 16; ++j) {
                bool isk = (g == kc) && (j == kj);
                float upd = fmaf(-f, pv[j], rM[j]);
                rM[j] = isk ? (-f * pv[j]) : upd;
            }
        }
    }

    // ================= Write Minv + tau =================
    {
        float* dst = minv_out + (size_t)blockIdx.x * (N_QP * N_QP) + c * 64 + 16 * g;
        *(float4*)&dst[0]  = make_float4(rM[0],  rM[1],  rM[2],  rM[3]);
        *(float4*)&dst[4]  = make_float4(rM[4],  rM[5],  rM[6],  rM[7]);
        *(float4*)&dst[8]  = make_float4(rM[8],  rM[9],  rM[10], rM[11]);
        *(float4*)&dst[12] = make_float4(rM[12], rM[13], rM[14], rM[15]);
    }
    if (t == 0) tau_out[blockIdx.x] = tau;
}

// ---------------------------------------------------------------------------
// Kernel B — QP loop only. 512 threads / item, spill-free register budget.
//   rHr[16]: thread t holds H[r][16*h4 + k],  r=t>>2, h4=t&3
//   rM [8] : thread t holds Minv[c][8*g8+j],  c=t>>3, g8=t&7
//   H^T matvec via sHT[col][row] (stride 128), strided columns 4*g8+32*i+j.
// ---------------------------------------------------------------------------
__global__ __launch_bounds__(512, 2)
void qp_kernel(const float* __restrict__ out3,
               const float* __restrict__ minv_in,
               const float* __restrict__ tau_in,
               float* __restrict__ xs)
{
    __shared__ __align__(16) float sHT[64 * 128];
    __shared__ __align__(16) float sxbar[64];
    __shared__ __align__(16) float stv[64];
    __shared__ __align__(16) float slam[128];
    __shared__ __align__(16) float sb[128];
    __shared__ __align__(16) float sq[64];

    const int t  = threadIdx.x;
    const int r  = t >> 2;   // 0..127
    const int h4 = t & 3;
    const int c  = t >> 3;   // 0..63
    const int g8 = t & 7;

    const float* row = out3 + (size_t)blockIdx.x * N_OUT;
    const unsigned FULL = 0xffffffffu;

    // ---- Load H row slices + scatter transposed copy ----
    float rHr[16];
    {
        const float4* base = (const float4*)(row + HOFF + r * 64 + 16 * h4);
        float4 v0 = base[0], v1 = base[1], v2 = base[2], v3 = base[3];
        rHr[0]=v0.x;  rHr[1]=v0.y;  rHr[2]=v0.z;  rHr[3]=v0.w;
        rHr[4]=v1.x;  rHr[5]=v1.y;  rHr[6]=v1.z;  rHr[7]=v1.w;
        rHr[8]=v2.x;  rHr[9]=v2.y;  rHr[10]=v2.z; rHr[11]=v2.w;
        rHr[12]=v3.x; rHr[13]=v3.y; rHr[14]=v3.z; rHr[15]=v3.w;
        float* dst = sHT + (16 * h4) * 128 + r;
        dst[0*128]=rHr[0];   dst[1*128]=rHr[1];   dst[2*128]=rHr[2];
        dst[3*128]=rHr[3];   dst[4*128]=rHr[4];   dst[5*128]=rHr[5];
        dst[6*128]=rHr[6];   dst[7*128]=rHr[7];   dst[8*128]=rHr[8];
        dst[9*128]=rHr[9];   dst[10*128]=rHr[10]; dst[11*128]=rHr[11];
        dst[12*128]=rHr[12]; dst[13*128]=rHr[13]; dst[14*128]=rHr[14];
        dst[15*128]=rHr[15];
    }

    // ---- Load Minv slice + tau ----
    float rM[8];
    {
        const float4* ms = (const float4*)(minv_in + (size_t)blockIdx.x * (N_QP * N_QP)
                                           + c * 64 + 8 * g8);
        float4 m0 = ms[0], m1 = ms[1];
        rM[0]=m0.x; rM[1]=m0.y; rM[2]=m0.z; rM[3]=m0.w;
        rM[4]=m1.x; rM[5]=m1.y; rM[6]=m1.z; rM[7]=m1.w;
    }
    const float tau = tau_in[blockIdx.x];
    const float sig = tau;

    if (t < 64)       { sq[t] = row[N_P + t]; sxbar[t] = 0.f; stv[t] = 0.f; }
    else if (t < 192) { sb[t - 64] = row[HOFF + N_HMAT + (t - 64)]; slam[t - 64] = 0.f; }
    float xp = 0.f;
    __syncthreads();

    for (int it = 0; it < QP_ITER; ++it) {
        {   // lam = relu(lam - sig*(H xbar + b))   (r, h4)
            const float4* x4 = (const float4*)(sxbar + 16 * h4);
            float4 x0 = x4[0], x1 = x4[1], x2 = x4[2], x3 = x4[3];
            float a0=0.f, a1=0.f, a2=0.f, a3=0.f;
            a0 = fmaf(rHr[0],  x0.x, a0); a1 = fmaf(rHr[1],  x0.y, a1);
            a2 = fmaf(rHr[2],  x0.z, a2); a3 = fmaf(rHr[3],  x0.w, a3);
            a0 = fmaf(rHr[4],  x1.x, a0); a1 = fmaf(rHr[5],  x1.y, a1);
            a2 = fmaf(rHr[6],  x1.z, a2); a3 = fmaf(rHr[7],  x1.w, a3);
            a0 = fmaf(rHr[8],  x2.x, a0); a1 = fmaf(rHr[9],  x2.y, a1);
            a2 = fmaf(rHr[10], x2.z, a2); a3 = fmaf(rHr[11], x2.w, a3);
            a0 = fmaf(rHr[12], x3.x, a0); a1 = fmaf(rHr[13], x3.y, a1);
            a2 = fmaf(rHr[14], x3.z, a2); a3 = fmaf(rHr[15], x3.w, a3);
            float s = (a0 + a1) + (a2 + a3);
            s += __shfl_xor_sync(FULL, s, 1);
            s += __shfl_xor_sync(FULL, s, 2);
            if (h4 == 0) slam[r] = fmaxf(0.f, slam[r] - sig * (s + sb[r]));
        }
        __syncthreads();
        {   // tvec = xp + tau*(H^T lam - q)   (c, g8) — strided columns
            float a0=0.f, a1=0.f, a2=0.f, a3=0.f;
            #pragma unroll
            for (int i = 0; i < 4; ++i) {
                float4 h = *(const float4*)&sHT[c * 128 + 4 * g8 + 32 * i];
                float4 l = *(const float4*)&slam[4 * g8 + 32 * i];
                a0 = fmaf(h.x, l.x, a0);
                a1 = fmaf(h.y, l.y, a1);
                a2 = fmaf(h.z, l.z, a2);
                a3 = fmaf(h.w, l.w, a3);
            }
            float p = (a0 + a1) + (a2 + a3);
            p += __shfl_xor_sync(FULL, p, 1);
            p += __shfl_xor_sync(FULL, p, 2);
            p += __shfl_xor_sync(FULL, p, 4);
            if (g8 == 0) stv[c] = xp + tau * (p - sq[c]);
        }
        __syncthreads();
        {   // xn = Minv tvec ; xbar = 2 xn - xp ; xp = xn   (c, g8)
            float4 t0 = *(const float4*)&stv[8 * g8];
            float4 t1 = *(const float4*)&stv[8 * g8 + 4];
            float a0=0.f, a1=0.f, a2=0.f, a3=0.f;
            a0 = fmaf(rM[0], t0.x, a0); a1 = fmaf(rM[1], t0.y, a1);
            a2 = fmaf(rM[2], t0.z, a2); a3 = fmaf(rM[3], t0.w, a3);
            a0 = fmaf(rM[4], t1.x, a0); a1 = fmaf(rM[5], t1.y, a1);
            a2 = fmaf(rM[6], t1.z, a2); a3 = fmaf(rM[7], t1.w, a3);
            float p = (a0 + a1) + (a2 + a3);
            p += __shfl_xor_sync(FULL, p, 1);
            p += __shfl_xor_sync(FULL, p, 2);
            p += __shfl_xor_sync(FULL, p, 4);
            if (g8 == 0) {
                sxbar[c] = 2.f * p - xp;
                xp = p;
            }
        }
        __syncthreads();
    }

    if (g8 == 0) xs[(size_t)blockIdx.x * N_QP + c] = xp;
}

// ---------------------------------------------------------------------------
// Launch
// ---------------------------------------------------------------------------
extern "C" void kernel_launch(void* const* d_in, const int* in_sizes, int n_in,
                              void* d_out, int out_size)
{
    const float* x  = (const float*)d_in[0];
    const float* W1 = (const float*)d_in[1];
    const float* b1 = (const float*)d_in[2];
    const float* W2 = (const float*)d_in[3];
    const float* b2 = (const float*)d_in[4];
    const float* W3 = (const float*)d_in[5];
    const float* b3 = (const float*)d_in[6];
    float* out = (float*)d_out;

    float *p_h1, *p_h2, *p_out3, *p_minv, *p_tau;
    cudaGetSymbolAddress((void**)&p_h1, g_h1);
    cudaGetSymbolAddress((void**)&p_h2, g_h2);
    cudaGetSymbolAddress((void**)&p_out3, g_out3);
    cudaGetSymbolAddress((void**)&p_minv, g_minv);
    cudaGetSymbolAddress((void**)&p_tau, g_tau);

    {
        dim3 grid(HIDDEN / 64, BATCH / 64);
        sgemm_bias<true><<<grid, 256>>>(x, W1, b1, p_h1, BATCH, HIDDEN, INPUT_SIZE);
    }
    {
        dim3 grid(HIDDEN / 64, BATCH / 64);
        sgemm_bias<true><<<grid, 256>>>(p_h1, W2, b2, p_h2, BATCH, HIDDEN, HIDDEN);
    }
    {
        dim3 grid((N_OUT + 63) / 64, BATCH / 64);
        sgemm_bias<false><<<grid, 256>>>(p_h2, W3, b3, p_out3, BATCH, N_OUT, HIDDEN);
    }
    {
        const size_t dyn_bytes = (size_t)SETUP_SMEM_FLOATS * sizeof(float);
        cudaFuncSetAttribute(setup_kernel,
                             cudaFuncAttributeMaxDynamicSharedMemorySize,
                             (int)dyn_bytes);
        setup_kernel<<<BATCH, 256, dyn_bytes>>>(p_out3, p_minv, p_tau);
    }
    qp_kernel<<<BATCH, 512>>>(p_out3, p_minv, p_tau, out);
}

// round 12
// speedup vs baseline: 2.2778x; 2.2778x over previous
#include <cuda_runtime.h>
#include <cuda_bf16.h>
#include <mma.h>
#include <math.h>

using namespace nvcuda;

#define BATCH 1024
#define INPUT_SIZE 512
#define HIDDEN 1024
#define N_QP 64
#define M_QP 128
#define QP_ITER 50
#define N_P 2080          // 64*65/2
#define N_HMAT 8192       // 128*64
#define N_OUT 10464       // 2080 + 64 + 8192 + 128
#define HOFF 2144         // N_P + N_QP

__device__ __align__(16) float g_h1[BATCH * HIDDEN];
__device__ __align__(16) float g_h2[BATCH * HIDDEN];
__device__ __align__(16) float g_out3[BATCH * N_OUT];

// ---------------------------------------------------------------------------
// Tiled fp32 SGEMM with fused bias + ReLU — used for GEMM1 and GEMM2 only.
// ---------------------------------------------------------------------------
template <bool RELU>
__global__ __launch_bounds__(256)
void sgemm_bias(const float* __restrict__ A, const float* __restrict__ B,
                const float* __restrict__ bias, float* __restrict__ C,
                int M, int N, int K)
{
    __shared__ float As[16 * 65];
    __shared__ float Bs[16 * 64];

    const int tid = threadIdx.x;
    const int tx = tid & 15;
    const int ty = tid >> 4;
    const int m0 = blockIdx.y * 64;
    const int n0 = blockIdx.x * 64;

    const int aRow = tid >> 2;
    const int aC4  = tid & 3;
    const int bRow = tid >> 4;
    const int bC4  = tid & 15;

    float acc[4][4] = {};

    for (int k0 = 0; k0 < K; k0 += 16) {
        float4 av = *(const float4*)&A[(size_t)(m0 + aRow) * K + k0 + aC4 * 4];
        int bn = n0 + bC4 * 4;
        float4 bv = make_float4(0.f, 0.f, 0.f, 0.f);
        if (bn < N) bv = *(const float4*)&B[(size_t)(k0 + bRow) * N + bn];

        __syncthreads();
        As[(aC4 * 4 + 0) * 65 + aRow] = av.x;
        As[(aC4 * 4 + 1) * 65 + aRow] = av.y;
        As[(aC4 * 4 + 2) * 65 + aRow] = av.z;
        As[(aC4 * 4 + 3) * 65 + aRow] = av.w;
        *(float4*)&Bs[bRow * 64 + bC4 * 4] = bv;
        __syncthreads();

        #pragma unroll
        for (int k = 0; k < 16; ++k) {
            float4 bb = *(const float4*)&Bs[k * 64 + tx * 4];
            float a0 = As[k * 65 + ty * 4 + 0];
            float a1 = As[k * 65 + ty * 4 + 1];
            float a2 = As[k * 65 + ty * 4 + 2];
            float a3 = As[k * 65 + ty * 4 + 3];
            acc[0][0] = fmaf(a0, bb.x, acc[0][0]);
            acc[0][1] = fmaf(a0, bb.y, acc[0][1]);
            acc[0][2] = fmaf(a0, bb.z, acc[0][2]);
            acc[0][3] = fmaf(a0, bb.w, acc[0][3]);
            acc[1][0] = fmaf(a1, bb.x, acc[1][0]);
            acc[1][1] = fmaf(a1, bb.y, acc[1][1]);
            acc[1][2] = fmaf(a1, bb.z, acc[1][2]);
            acc[1][3] = fmaf(a1, bb.w, acc[1][3]);
            acc[2][0] = fmaf(a2, bb.x, acc[2][0]);
            acc[2][1] = fmaf(a2, bb.y, acc[2][1]);
            acc[2][2] = fmaf(a2, bb.z, acc[2][2]);
            acc[2][3] = fmaf(a2, bb.w, acc[2][3]);
            acc[3][0] = fmaf(a3, bb.x, acc[3][0]);
            acc[3][1] = fmaf(a3, bb.y, acc[3][1]);
            acc[3][2] = fmaf(a3, bb.z, acc[3][2]);
            acc[3][3] = fmaf(a3, bb.w, acc[3][3]);
        }
    }

    #pragma unroll
    for (int ii = 0; ii < 4; ++ii) {
        int m = m0 + ty * 4 + ii;
        #pragma unroll
        for (int jj = 0; jj < 4; ++jj) {
            int n = n0 + tx * 4 + jj;
            if (n < N) {
                float v = acc[ii][jj] + bias[n];
                if (RELU) v = fmaxf(v, 0.f);
                C[(size_t)m * N + n] = v;
            }
        }
    }
}

// ---------------------------------------------------------------------------
// GEMM3 via tensor cores: bf16 2-way split (hi/lo), fp32 accumulate.
// C = A @ B + bias,  M=1024, N=10464 (=109*96), K=1024.
// CTA tile 128x96, 8 warps (4x2), warp tile 32x48, k-step 16.
// ---------------------------------------------------------------------------
#define G3_N   10464
#define G3_K   1024
#define G3_AS  24    // A smem stride (bf16 elems), 48B = 3*16B
#define G3_BS  104   // B smem stride (bf16 elems), 208B = 13*16B
#define G3_SN  100   // C staging stride (floats)
#define G3_SMEM_BYTES (128 * G3_SN * 4)   // 51200 B (covers A/B phase too)

__device__ __forceinline__ void split_bf16(float v, __nv_bfloat16& h, __nv_bfloat16& l)
{
    h = __float2bfloat16(v);
    l = __float2bfloat16(v - __bfloat162float(h));
}

__global__ __launch_bounds__(256, 2)
void gemm3_wmma(const float* __restrict__ A, const float* __restrict__ B,
                const float* __restrict__ bias, float* __restrict__ C)
{
    extern __shared__ __align__(16) unsigned char smraw[];
    __nv_bfloat16* sA_hi = (__nv_bfloat16*)smraw;                 // 128*24
    __nv_bfloat16* sA_lo = sA_hi + 128 * G3_AS;                   // 128*24
    __nv_bfloat16* sB_hi = sA_lo + 128 * G3_AS;                   // 16*104
    __nv_bfloat16* sB_lo = sB_hi + 16 * G3_BS;                    // 16*104
    float* sC = (float*)smraw;                                    // 128*100 (epilogue)

    const int t    = threadIdx.x;
    const int warp = t >> 5;
    const int wm   = warp & 3;    // 0..3 -> 32 rows each
    const int wn   = warp >> 2;   // 0..1 -> 48 cols each
    const int n0   = blockIdx.x * 96;
    const int m0   = blockIdx.y * 128;

    wmma::fragment<wmma::accumulator, 16, 16, 16, float> acc[2][3];
    #pragma unroll
    for (int i = 0; i < 2; ++i)
        #pragma unroll
        for (int j = 0; j < 3; ++j)
            wmma::fill_fragment(acc[i][j], 0.f);

    for (int k0 = 0; k0 < G3_K; k0 += 16) {
        __syncthreads();   // previous iteration's frag loads done
        // ---- A tile 128x16 fp32 -> bf16 hi/lo (512 float4, 2/thread) ----
        #pragma unroll
        for (int i = 0; i < 2; ++i) {
            int l4  = t * 2 + i;          // 0..511
            int row = l4 >> 2;            // 0..127
            int c4  = (l4 & 3) * 4;       // 0,4,8,12
            float4 v = *(const float4*)&A[(size_t)(m0 + row) * G3_K + k0 + c4];
            __nv_bfloat16 h0, l0, h1, l1, h2, l2, h3, l3;
            split_bf16(v.x, h0, l0); split_bf16(v.y, h1, l1);
            split_bf16(v.z, h2, l2); split_bf16(v.w, h3, l3);
            __nv_bfloat16* dh = sA_hi + row * G3_AS + c4;
            __nv_bfloat16* dl = sA_lo + row * G3_AS + c4;
            dh[0] = h0; dh[1] = h1; dh[2] = h2; dh[3] = h3;
            dl[0] = l0; dl[1] = l1; dl[2] = l2; dl[3] = l3;
        }
        // ---- B tile 16x96 fp32 -> bf16 hi/lo (384 float4, threads 0..191) ----
        if (t < 192) {
            #pragma unroll
            for (int i = 0; i < 2; ++i) {
                int l4  = t * 2 + i;      // 0..383
                int row = l4 / 24;        // 0..15
                int c4  = (l4 % 24) * 4;  // 0..92
                float4 v = *(const float4*)&B[(size_t)(k0 + row) * G3_N + n0 + c4];
                __nv_bfloat16 h0, l0, h1, l1, h2, l2, h3, l3;
                split_bf16(v.x, h0, l0); split_bf16(v.y, h1, l1);
                split_bf16(v.z, h2, l2); split_bf16(v.w, h3, l3);
                __nv_bfloat16* dh = sB_hi + row * G3_BS + c4;
                __nv_bfloat16* dl = sB_lo + row * G3_BS + c4;
                dh[0] = h0; dh[1] = h1; dh[2] = h2; dh[3] = h3;
                dl[0] = l0; dl[1] = l1; dl[2] = l2; dl[3] = l3;
            }
        }
        __syncthreads();

        wmma::fragment<wmma::matrix_a, 16, 16, 16, __nv_bfloat16, wmma::row_major> a_hi[2], a_lo[2];
        wmma::fragment<wmma::matrix_b, 16, 16, 16, __nv_bfloat16, wmma::row_major> b_hi[3], b_lo[3];
        #pragma unroll
        for (int i = 0; i < 2; ++i) {
            wmma::load_matrix_sync(a_hi[i], sA_hi + (wm * 32 + i * 16) * G3_AS, G3_AS);
            wmma::load_matrix_sync(a_lo[i], sA_lo + (wm * 32 + i * 16) * G3_AS, G3_AS);
        }
        #pragma unroll
        for (int j = 0; j < 3; ++j) {
            wmma::load_matrix_sync(b_hi[j], sB_hi + wn * 48 + j * 16, G3_BS);
            wmma::load_matrix_sync(b_lo[j], sB_lo + wn * 48 + j * 16, G3_BS);
        }
        #pragma unroll
        for (int i = 0; i < 2; ++i)
            #pragma unroll
            for (int j = 0; j < 3; ++j) {
                wmma::mma_sync(acc[i][j], a_hi[i], b_hi[j], acc[i][j]);
                wmma::mma_sync(acc[i][j], a_hi[i], b_lo[j], acc[i][j]);
                wmma::mma_sync(acc[i][j], a_lo[i], b_hi[j], acc[i][j]);
            }
    }

    // ---- Epilogue: stage accs in smem, add bias, coalesced store ----
    __syncthreads();
    #pragma unroll
    for (int i = 0; i < 2; ++i)
        #pragma unroll
        for (int j = 0; j < 3; ++j)
            wmma::store_matrix_sync(sC + (wm * 32 + i * 16) * G3_SN + wn * 48 + j * 16,
                                    acc[i][j], G3_SN, wmma::mem_row_major);
    __syncthreads();
    for (int l = t; l < 128 * 96; l += 256) {
        int row = l / 96, col = l % 96;
        C[(size_t)(m0 + row) * G3_N + n0 + col] = sC[row * G3_SN + col] + bias[n0 + col];
    }
}

// ---------------------------------------------------------------------------
// QP solver — round-4 version verbatim (proven: 441 us). 256 thr / item.
// ---------------------------------------------------------------------------
__device__ __forceinline__ float sel16(const float* r, int kj) {
    float v = r[0];
    #pragma unroll
    for (int j = 1; j < 16; ++j) v = (j == kj) ? r[j] : v;
    return v;
}

#define SOLVER_SMEM_FLOATS (128 * 65 + 64 * 65)

__global__ __launch_bounds__(256, 2)
void solver_kernel(const float* __restrict__ out3, float* __restrict__ xs)
{
    extern __shared__ __align__(16) float smdyn[];
    float* sH = smdyn;              // 128*65  (H, persistent)
    float* sQ = sH + 128 * 65;      // 64*65   (L, then dead)

    __shared__ __align__(16) float spiv[2 * 64];
    __shared__ __align__(16) float sxbar[64];
    __shared__ __align__(16) float st[64];
    __shared__ __align__(16) float slam[128];
    __shared__ __align__(16) float sb[128];
    __shared__ __align__(16) float sq[64];
    __shared__ __align__(16) float sv[64];
    __shared__ __align__(16) float sw[128];
    __shared__ float spart[8];
    __shared__ float s_scal, s_tau;

    const int t    = threadIdx.x;
    const int lane = t & 31;
    const int warp = t >> 5;
    const int r    = t >> 1;   // 0..127
    const int h    = t & 1;
    const int c    = t >> 2;   // 0..63
    const int g    = t & 3;

    const float* row = out3 + (size_t)blockIdx.x * N_OUT;
    const unsigned FULL = 0xffffffffu;

    float rH[32];
    {
        const float4* base = (const float4*)(row + HOFF + r * 64 + 32 * h);
        #pragma unroll
        for (int k4 = 0; k4 < 8; ++k4) {
            float4 v = base[k4];
            rH[4*k4+0] = v.x; rH[4*k4+1] = v.y; rH[4*k4+2] = v.z; rH[4*k4+3] = v.w;
            sH[r * 65 + 32 * h + 4 * k4 + 0] = v.x;
            sH[r * 65 + 32 * h + 4 * k4 + 1] = v.y;
            sH[r * 65 + 32 * h + 4 * k4 + 2] = v.z;
            sH[r * 65 + 32 * h + 4 * k4 + 3] = v.w;
        }
    }
    if (t < 64)  sq[t] = row[N_P + t];
    if (t < 128) sb[t] = row[HOFF + N_HMAT + t];
    if (t < 64)  sv[t] = 0.125f;
    __syncthreads();

    for (int pit = 0; pit < 10; ++pit) {
        {
            const float4* x4 = (const float4*)(sv + 32 * h);
            float a0=0.f,a1=0.f,a2=0.f,a3=0.f;
            #pragma unroll
            for (int k4 = 0; k4 < 8; ++k4) {
                float4 xv = x4[k4];
                a0 = fmaf(rH[4*k4+0], xv.x, a0);
                a1 = fmaf(rH[4*k4+1], xv.y, a1);
                a2 = fmaf(rH[4*k4+2], xv.z, a2);
                a3 = fmaf(rH[4*k4+3], xv.w, a3);
            }
            float s = (a0 + a1) + (a2 + a3);
            s += __shfl_xor_sync(FULL, s, 1);
            if (h == 0) sw[r] = s;
        }
        __syncthreads();
        {
            float a0=0.f,a1=0.f,a2=0.f,a3=0.f;
            #pragma unroll
            for (int j0 = 0; j0 < 32; j0 += 4) {
                int jj0 = (j0 + 0 + 8 * g) & 31;
                int jj1 = (j0 + 1 + 8 * g) & 31;
                int jj2 = (j0 + 2 + 8 * g) & 31;
                int jj3 = (j0 + 3 + 8 * g) & 31;
                a0 = fmaf(sH[(32*g + jj0) * 65 + c], sw[32*g + jj0], a0);
                a1 = fmaf(sH[(32*g + jj1) * 65 + c], sw[32*g + jj1], a1);
                a2 = fmaf(sH[(32*g + jj2) * 65 + c], sw[32*g + jj2], a2);
                a3 = fmaf(sH[(32*g + jj3) * 65 + c], sw[32*g + jj3], a3);
            }
            float p = (a0 + a1) + (a2 + a3);
            p += __shfl_xor_sync(FULL, p, 1);
            p += __shfl_xor_sync(FULL, p, 2);
            float pp = (g == 0) ? p * p : 0.f;
            #pragma unroll
            for (int off = 16; off >= 1; off >>= 1)
                pp += __shfl_xor_sync(FULL, pp, off);
            if (lane == 0) spart[warp] = pp;
            __syncthreads();
            if (t == 0) {
                float sm = 0.f;
                #pragma unroll
                for (int i = 0; i < 8; ++i) sm += spart[i];
                s_scal = sqrtf(sm) + 1e-12f;
            }
            __syncthreads();
            if (g == 0) sv[c] = p / s_scal;
        }
        __syncthreads();
    }

    {
        const float4* x4 = (const float4*)(sv + 32 * h);
        float a0=0.f,a1=0.f,a2=0.f,a3=0.f;
        #pragma unroll
        for (int k4 = 0; k4 < 8; ++k4) {
            float4 xv = x4[k4];
            a0 = fmaf(rH[4*k4+0], xv.x, a0);
            a1 = fmaf(rH[4*k4+1], xv.y, a1);
            a2 = fmaf(rH[4*k4+2], xv.z, a2);
            a3 = fmaf(rH[4*k4+3], xv.w, a3);
        }
        float s = (a0 + a1) + (a2 + a3);
        s += __shfl_xor_sync(FULL, s, 1);
        float pp = (h == 0) ? s * s : 0.f;
        #pragma unroll
        for (int off = 16; off >= 1; off >>= 1)
            pp += __shfl_xor_sync(FULL, pp, off);
        if (lane == 0) spart[warp] = pp;
        __syncthreads();
        if (t == 0) {
            float sm = 0.f;
            #pragma unroll
            for (int i = 0; i < 8; ++i) sm += spart[i];
            s_tau = 0.9f / (sqrtf(sm) + 1e-6f);
        }
    }

    for (int idx = t; idx < 64 * 65; idx += 256) sQ[idx] = 0.f;
    __syncthreads();
    for (int idx = t; idx < N_P; idx += 256) {
        float p = row[idx];
        int rr = (int)((sqrtf(8.f * (float)idx + 1.f) - 1.f) * 0.5f);
        while ((rr * (rr + 1)) / 2 > idx) --rr;
        while (((rr + 1) * (rr + 2)) / 2 <= idx) ++rr;
        int cc = idx - (rr * (rr + 1)) / 2;
        float val;
        if (cc == rr) {
            float sp = fmaxf(p, 0.f) + log1pf(expf(-fabsf(p)));
            val = 0.1f + sp;
        } else {
            val = p;
        }
        sQ[rr * 65 + cc] = val;
    }
    __syncthreads();
    const float tau = s_tau;
    const float sig = tau;

    float rM[16];
    #pragma unroll
    for (int j = 0; j < 16; ++j) rM[j] = 0.f;
    for (int k = 0; k < 64; ++k) {
        float a = sQ[c * 65 + k];
        #pragma unroll
        for (int j = 0; j < 16; ++j)
            rM[j] = fmaf(a, sQ[(16 * g + j) * 65 + k], rM[j]);
    }
    #pragma unroll
    for (int j = 0; j < 16; ++j) {
        int col = 16 * g + j;
        rM[j] = tau * rM[j] + ((col == c) ? 1.f : 0.f);
    }
    __syncthreads();

    for (int k = 0; k < 64; ++k) {
        const int kc = k >> 4, kj = k & 15;
        float* buf = spiv + (k & 1) * 64;
        float praw = __shfl_sync(FULL, sel16(rM, kj), (lane & ~3) | kc);
        if (c == k) {
            float pinv = 1.f / praw;
            #pragma unroll
            for (int j = 0; j < 16; ++j) {
                bool isk = (g == kc) && (j == kj);
                rM[j] = isk ? pinv : rM[j] * pinv;
            }
            *(float4*)&buf[16*g +  0] = make_float4(rM[0],  rM[1],  rM[2],  rM[3]);
            *(float4*)&buf[16*g +  4] = make_float4(rM[4],  rM[5],  rM[6],  rM[7]);
            *(float4*)&buf[16*g +  8] = make_float4(rM[8],  rM[9],  rM[10], rM[11]);
            *(float4*)&buf[16*g + 12] = make_float4(rM[12], rM[13], rM[14], rM[15]);
        }
        __syncthreads();
        if (c != k) {
            const float f = praw;
            float4 p0 = *(const float4*)&buf[16*g +  0];
            float4 p1 = *(const float4*)&buf[16*g +  4];
            float4 p2 = *(const float4*)&buf[16*g +  8];
            float4 p3 = *(const float4*)&buf[16*g + 12];
            float pv[16] = {p0.x,p0.y,p0.z,p0.w, p1.x,p1.y,p1.z,p1.w,
                            p2.x,p2.y,p2.z,p2.w, p3.x,p3.y,p3.z,p3.w};
            #pragma unroll
            for (int j = 0; j < 16; ++j) {
                bool isk = (g == kc) && (j == kj);
                float upd = fmaf(-f, pv[j], rM[j]);
                rM[j] = isk ? (-f * pv[j]) : upd;
            }
        }
    }
    __syncthreads();

    if (t < 64)  { sxbar[t] = 0.f; st[t] = 0.f; }
    if (t < 128) slam[t] = 0.f;
    float xp = 0.f;
    __syncthreads();

    for (int it = 0; it < QP_ITER; ++it) {
        {
            const float4* x4 = (const float4*)(sxbar + 32 * h);
            float a0=0.f,a1=0.f,a2=0.f,a3=0.f;
            #pragma unroll
            for (int k4 = 0; k4 < 8; ++k4) {
                float4 xv = x4[k4];
                a0 = fmaf(rH[4*k4+0], xv.x, a0);
                a1 = fmaf(rH[4*k4+1], xv.y, a1);
                a2 = fmaf(rH[4*k4+2], xv.z, a2);
                a3 = fmaf(rH[4*k4+3], xv.w, a3);
            }
            float s = (a0 + a1) + (a2 + a3);
            s += __shfl_xor_sync(FULL, s, 1);
            if (h == 0) slam[r] = fmaxf(0.f, slam[r] - sig * (s + sb[r]));
        }
        __syncthreads();
        {
            float a0=0.f,a1=0.f,a2=0.f,a3=0.f;
            #pragma unroll
            for (int j0 = 0; j0 < 32; j0 += 4) {
                int jj0 = (j0 + 0 + 8 * g) & 31;
                int jj1 = (j0 + 1 + 8 * g) & 31;
                int jj2 = (j0 + 2 + 8 * g) & 31;
                int jj3 = (j0 + 3 + 8 * g) & 31;
                a0 = fmaf(sH[(32*g + jj0) * 65 + c], slam[32*g + jj0], a0);
                a1 = fmaf(sH[(32*g + jj1) * 65 + c], slam[32*g + jj1], a1);
                a2 = fmaf(sH[(32*g + jj2) * 65 + c], slam[32*g + jj2], a2);
                a3 = fmaf(sH[(32*g + jj3) * 65 + c], slam[32*g + jj3], a3);
            }
            float p = (a0 + a1) + (a2 + a3);
            p += __shfl_xor_sync(FULL, p, 1);
            p += __shfl_xor_sync(FULL, p, 2);
            if (g == 0) st[c] = xp + tau * (p - sq[c]);
        }
        __syncthreads();
        {
            const float4* t4 = (const float4*)(st + 16 * g);
            float4 t0 = t4[0], t1 = t4[1], t2 = t4[2], t3 = t4[3];
            float a0=0.f,a1=0.f,a2=0.f,a3=0.f;
            a0 = fmaf(rM[0],  t0.x, a0); a1 = fmaf(rM[1],  t0.y, a1);
            a2 = fmaf(rM[2],  t0.z, a2); a3 = fmaf(rM[3],  t0.w, a3);
            a0 = fmaf(rM[4],  t1.x, a0); a1 = fmaf(rM[5],  t1.y, a1);
            a2 = fmaf(rM[6],  t1.z, a2); a3 = fmaf(rM[7],  t1.w, a3);
            a0 = fmaf(rM[8],  t2.x, a0); a1 = fmaf(rM[9],  t2.y, a1);
            a2 = fmaf(rM[10], t2.z, a2); a3 = fmaf(rM[11], t2.w, a3);
            a0 = fmaf(rM[12], t3.x, a0); a1 = fmaf(rM[13], t3.y, a1);
            a2 = fmaf(rM[14], t3.z, a2); a3 = fmaf(rM[15], t3.w, a3);
            float p = (a0 + a1) + (a2 + a3);
            p += __shfl_xor_sync(FULL, p, 1);
            p += __shfl_xor_sync(FULL, p, 2);
            if (g == 0) {
                sxbar[c] = 2.f * p - xp;
                xp = p;
            }
        }
        __syncthreads();
    }

    if (g == 0) xs[(size_t)blockIdx.x * N_QP + c] = xp;
}

// ---------------------------------------------------------------------------
// Launch
// ---------------------------------------------------------------------------
extern "C" void kernel_launch(void* const* d_in, const int* in_sizes, int n_in,
                              void* d_out, int out_size)
{
    const float* x  = (const float*)d_in[0];
    const float* W1 = (const float*)d_in[1];
    const float* b1 = (const float*)d_in[2];
    const float* W2 = (const float*)d_in[3];
    const float* b2 = (const float*)d_in[4];
    const float* W3 = (const float*)d_in[5];
    const float* b3 = (const float*)d_in[6];
    float* out = (float*)d_out;

    float *p_h1, *p_h2, *p_out3;
    cudaGetSymbolAddress((void**)&p_h1, g_h1);
    cudaGetSymbolAddress((void**)&p_h2, g_h2);
    cudaGetSymbolAddress((void**)&p_out3, g_out3);

    {
        dim3 grid(HIDDEN / 64, BATCH / 64);
        sgemm_bias<true><<<grid, 256>>>(x, W1, b1, p_h1, BATCH, HIDDEN, INPUT_SIZE);
    }
    {
        dim3 grid(HIDDEN / 64, BATCH / 64);
        sgemm_bias<true><<<grid, 256>>>(p_h1, W2, b2, p_h2, BATCH, HIDDEN, HIDDEN);
    }
    {
        cudaFuncSetAttribute(gemm3_wmma,
                             cudaFuncAttributeMaxDynamicSharedMemorySize,
                             G3_SMEM_BYTES);
        dim3 grid(G3_N / 96, BATCH / 128);   // 109 x 8
        gemm3_wmma<<<grid, 256, G3_SMEM_BYTES>>>(p_h2, W3, b3, p_out3);
    }
    {
        const size_t smem_bytes = (size_t)SOLVER_SMEM_FLOATS * sizeof(float);
        cudaFuncSetAttribute(solver_kernel,
                             cudaFuncAttributeMaxDynamicSharedMemorySize,
                             (int)smem_bytes);
        solver_kernel<<<BATCH, 256, smem_bytes>>>(p_out3, out);
    }
}

// round 14
// speedup vs baseline: 2.3483x; 1.0309x over previous
#include <cuda_runtime.h>
#include <cuda_bf16.h>
#include <mma.h>
#include <math.h>

using namespace nvcuda;

#define BATCH 1024
#define INPUT_SIZE 512
#define HIDDEN 1024
#define N_QP 64
#define M_QP 128
#define QP_ITER 50
#define N_P 2080          // 64*65/2
#define N_HMAT 8192       // 128*64
#define N_OUT 10464       // 2080 + 64 + 8192 + 128
#define HOFF 2144         // N_P + N_QP

__device__ __align__(16) float g_h1[BATCH * HIDDEN];
__device__ __align__(16) float g_h2[BATCH * HIDDEN];
__device__ __align__(16) float g_out3[BATCH * N_OUT];
// bf16 hi/lo split buffers for tensor-core GEMM3
__device__ __align__(16) __nv_bfloat16 g_a_hi[BATCH * HIDDEN];
__device__ __align__(16) __nv_bfloat16 g_a_lo[BATCH * HIDDEN];
__device__ __align__(16) __nv_bfloat16 g_b_hi[HIDDEN * N_OUT];
__device__ __align__(16) __nv_bfloat16 g_b_lo[HIDDEN * N_OUT];

// ---------------------------------------------------------------------------
// Tiled fp32 SGEMM with fused bias + ReLU — GEMM1 and GEMM2 only.
// ---------------------------------------------------------------------------
template <bool RELU>
__global__ __launch_bounds__(256)
void sgemm_bias(const float* __restrict__ A, const float* __restrict__ B,
                const float* __restrict__ bias, float* __restrict__ C,
                int M, int N, int K)
{
    __shared__ float As[16 * 65];
    __shared__ float Bs[16 * 64];

    const int tid = threadIdx.x;
    const int tx = tid & 15;
    const int ty = tid >> 4;
    const int m0 = blockIdx.y * 64;
    const int n0 = blockIdx.x * 64;

    const int aRow = tid >> 2;
    const int aC4  = tid & 3;
    const int bRow = tid >> 4;
    const int bC4  = tid & 15;

    float acc[4][4] = {};

    for (int k0 = 0; k0 < K; k0 += 16) {
        float4 av = *(const float4*)&A[(size_t)(m0 + aRow) * K + k0 + aC4 * 4];
        int bn = n0 + bC4 * 4;
        float4 bv = make_float4(0.f, 0.f, 0.f, 0.f);
        if (bn < N) bv = *(const float4*)&B[(size_t)(k0 + bRow) * N + bn];

        __syncthreads();
        As[(aC4 * 4 + 0) * 65 + aRow] = av.x;
        As[(aC4 * 4 + 1) * 65 + aRow] = av.y;
        As[(aC4 * 4 + 2) * 65 + aRow] = av.z;
        As[(aC4 * 4 + 3) * 65 + aRow] = av.w;
        *(float4*)&Bs[bRow * 64 + bC4 * 4] = bv;
        __syncthreads();

        #pragma unroll
        for (int k = 0; k < 16; ++k) {
            float4 bb = *(const float4*)&Bs[k * 64 + tx * 4];
            float a0 = As[k * 65 + ty * 4 + 0];
            float a1 = As[k * 65 + ty * 4 + 1];
            float a2 = As[k * 65 + ty * 4 + 2];
            float a3 = As[k * 65 + ty * 4 + 3];
            acc[0][0] = fmaf(a0, bb.x, acc[0][0]);
            acc[0][1] = fmaf(a0, bb.y, acc[0][1]);
            acc[0][2] = fmaf(a0, bb.z, acc[0][2]);
            acc[0][3] = fmaf(a0, bb.w, acc[0][3]);
            acc[1][0] = fmaf(a1, bb.x, acc[1][0]);
            acc[1][1] = fmaf(a1, bb.y, acc[1][1]);
            acc[1][2] = fmaf(a1, bb.z, acc[1][2]);
            acc[1][3] = fmaf(a1, bb.w, acc[1][3]);
            acc[2][0] = fmaf(a2, bb.x, acc[2][0]);
            acc[2][1] = fmaf(a2, bb.y, acc[2][1]);
            acc[2][2] = fmaf(a2, bb.z, acc[2][2]);
            acc[2][3] = fmaf(a2, bb.w, acc[2][3]);
            acc[3][0] = fmaf(a3, bb.x, acc[3][0]);
            acc[3][1] = fmaf(a3, bb.y, acc[3][1]);
            acc[3][2] = fmaf(a3, bb.z, acc[3][2]);
            acc[3][3] = fmaf(a3, bb.w, acc[3][3]);
        }
    }

    #pragma unroll
    for (int ii = 0; ii < 4; ++ii) {
        int m = m0 + ty * 4 + ii;
        #pragma unroll
        for (int jj = 0; jj < 4; ++jj) {
            int n = n0 + tx * 4 + jj;
            if (n < N) {
                float v = acc[ii][jj] + bias[n];
                if (RELU) v = fmaxf(v, 0.f);
                C[(size_t)m * N + n] = v;
            }
        }
    }
}

// ---------------------------------------------------------------------------
// fp32 -> bf16 hi/lo split (elementwise, vectorized). n4 = count/4.
// ---------------------------------------------------------------------------
__device__ __forceinline__ void split_bf16(float v, __nv_bfloat16& h, __nv_bfloat16& l)
{
    h = __float2bfloat16(v);
    l = __float2bfloat16(v - __bfloat162float(h));
}

__device__ __forceinline__ unsigned pack2(__nv_bfloat16 a, __nv_bfloat16 b)
{
    __nv_bfloat162 t(a, b);
    return *(unsigned*)&t;
}

__global__ __launch_bounds__(256)
void split_kernel(const float* __restrict__ in,
                  __nv_bfloat16* __restrict__ hi,
                  __nv_bfloat16* __restrict__ lo, int n4)
{
    int i = blockIdx.x * 256 + threadIdx.x;
    if (i >= n4) return;
    float4 v = ((const float4*)in)[i];
    __nv_bfloat16 h0, l0, h1, l1, h2, l2, h3, l3;
    split_bf16(v.x, h0, l0); split_bf16(v.y, h1, l1);
    split_bf16(v.z, h2, l2); split_bf16(v.w, h3, l3);
    ((uint2*)hi)[i] = make_uint2(pack2(h0, h1), pack2(h2, h3));
    ((uint2*)lo)[i] = make_uint2(pack2(l0, l1), pack2(l2, l3));
}

// ---------------------------------------------------------------------------
// GEMM3 tensor cores, pre-split bf16 inputs. C = A@B + bias (fp32 out).
// M=1024, N=10464 (=109*96), K=1024. CTA tile 128x96, k-step 32,
// 8 warps (4x2), warp tile 32x48.
// ---------------------------------------------------------------------------
#define G3_N   10464
#define G3_K   1024
#define G3_AS  40    // A smem stride in bf16 (80 B)
#define G3_BS  104   // B smem stride in bf16 (208 B)
#define G3_SN  100   // C staging stride (floats)
#define G3_SMEM_BYTES (128 * G3_SN * 4)   // 51200 B (>= tile phase usage 33.8 KB)

__global__ __launch_bounds__(256, 2)
void gemm3_bf16(const __nv_bfloat16* __restrict__ Ah, const __nv_bfloat16* __restrict__ Al,
                const __nv_bfloat16* __restrict__ Bh, const __nv_bfloat16* __restrict__ Bl,
                const float* __restrict__ bias, float* __restrict__ C)
{
    extern __shared__ __align__(16) unsigned char smraw[];
    __nv_bfloat16* sA_hi = (__nv_bfloat16*)smraw;        // 128*40
    __nv_bfloat16* sA_lo = sA_hi + 128 * G3_AS;          // 128*40
    __nv_bfloat16* sB_hi = sA_lo + 128 * G3_AS;          // 32*104
    __nv_bfloat16* sB_lo = sB_hi + 32 * G3_BS;           // 32*104
    float* sC = (float*)smraw;                           // 128*100 (epilogue)

    const int t    = threadIdx.x;
    const int warp = t >> 5;
    const int wm   = warp & 3;    // 0..3 -> 32 rows
    const int wn   = warp >> 2;   // 0..1 -> 48 cols
    const int n0   = blockIdx.x * 96;
    const int m0   = blockIdx.y * 128;

    wmma::fragment<wmma::accumulator, 16, 16, 16, float> acc[2][3];
    #pragma unroll
    for (int i = 0; i < 2; ++i)
        #pragma unroll
        for (int j = 0; j < 3; ++j)
            wmma::fill_fragment(acc[i][j], 0.f);

    for (int k0 = 0; k0 < G3_K; k0 += 32) {
        __syncthreads();
        // ---- A tiles 128x32 bf16 hi+lo: 512 uint4 each, 2/thread each ----
        #pragma unroll
        for (int i = 0; i < 2; ++i) {
            int l   = t * 2 + i;          // 0..511
            int row = l >> 2;             // 0..127
            int c8  = (l & 3) * 8;        // 0,8,16,24
            size_t src = (size_t)(m0 + row) * G3_K + k0 + c8;
            *(uint4*)(sA_hi + row * G3_AS + c8) = *(const uint4*)(Ah + src);
            *(uint4*)(sA_lo + row * G3_AS + c8) = *(const uint4*)(Al + src);
        }
        // ---- B tiles 32x96 bf16 hi+lo: 384 uint4 each = 768 total, 3/thread ----
        #pragma unroll
        for (int i = 0; i < 3; ++i) {
            int l   = t + 256 * i;        // 0..767
            int mat = (l >= 384);
            int ll  = l - mat * 384;
            int row = ll / 12;            // 0..31
            int c8  = (ll % 12) * 8;      // 0..88
            const __nv_bfloat16* src = mat ? Bl : Bh;
            __nv_bfloat16*       dst = mat ? sB_lo : sB_hi;
            *(uint4*)(dst + row * G3_BS + c8) =
                *(const uint4*)(src + (size_t)(k0 + row) * G3_N + n0 + c8);
        }
        __syncthreads();

        #pragma unroll
        for (int ks = 0; ks < 32; ks += 16) {
            wmma::fragment<wmma::matrix_a, 16, 16, 16, __nv_bfloat16, wmma::row_major> a_hi[2], a_lo[2];
            wmma::fragment<wmma::matrix_b, 16, 16, 16, __nv_bfloat16, wmma::row_major> b_hi[3], b_lo[3];
            #pragma unroll
            for (int i = 0; i < 2; ++i) {
                wmma::load_matrix_sync(a_hi[i], sA_hi + (wm * 32 + i * 16) * G3_AS + ks, G3_AS);
                wmma::load_matrix_sync(a_lo[i], sA_lo + (wm * 32 + i * 16) * G3_AS + ks, G3_AS);
            }
            #pragma unroll
            for (int j = 0; j < 3; ++j) {
                wmma::load_matrix_sync(b_hi[j], sB_hi + ks * G3_BS + wn * 48 + j * 16, G3_BS);
                wmma::load_matrix_sync(b_lo[j], sB_lo + ks * G3_BS + wn * 48 + j * 16, G3_BS);
            }
            #pragma unroll
            for (int i = 0; i < 2; ++i)
                #pragma unroll
                for (int j = 0; j < 3; ++j) {
                    wmma::mma_sync(acc[i][j], a_hi[i], b_hi[j], acc[i][j]);
                    wmma::mma_sync(acc[i][j], a_hi[i], b_lo[j], acc[i][j]);
                    wmma::mma_sync(acc[i][j], a_lo[i], b_hi[j], acc[i][j]);
                }
        }
    }

    // ---- Epilogue: stage in smem, add bias, coalesced store ----
    __syncthreads();
    #pragma unroll
    for (int i = 0; i < 2; ++i)
        #pragma unroll
        for (int j = 0; j < 3; ++j)
            wmma::store_matrix_sync(sC + (wm * 32 + i * 16) * G3_SN + wn * 48 + j * 16,
                                    acc[i][j], G3_SN, wmma::mem_row_major);
    __syncthreads();
    for (int l = t; l < 128 * 96; l += 256) {
        int row = l / 96, col = l % 96;
        C[(size_t)(m0 + row) * G3_N + n0 + col] = sC[row * G3_SN + col] + bias[n0 + col];
    }
}

// ---------------------------------------------------------------------------
// QP solver — round-4 version verbatim (proven: 441 us). 256 thr / item.
// ---------------------------------------------------------------------------
__device__ __forceinline__ float sel16(const float* r, int kj) {
    float v = r[0];
    #pragma unroll
    for (int j = 1; j < 16; ++j) v = (j == kj) ? r[j] : v;
    return v;
}

#define SOLVER_SMEM_FLOATS (128 * 65 + 64 * 65)

__global__ __launch_bounds__(256, 2)
void solver_kernel(const float* __restrict__ out3, float* __restrict__ xs)
{
    extern __shared__ __align__(16) float smdyn[];
    float* sH = smdyn;              // 128*65
    float* sQ = sH + 128 * 65;      // 64*65

    __shared__ __align__(16) float spiv[2 * 64];
    __shared__ __align__(16) float sxbar[64];
    __shared__ __align__(16) float st[64];
    __shared__ __align__(16) float slam[128];
    __shared__ __align__(16) float sb[128];
    __shared__ __align__(16) float sq[64];
    __shared__ __align__(16) float sv[64];
    __shared__ __align__(16) float sw[128];
    __shared__ float spart[8];
    __shared__ float s_scal, s_tau;

    const int t    = threadIdx.x;
    const int lane = t & 31;
    const int warp = t >> 5;
    const int r    = t >> 1;
    const int h    = t & 1;
    const int c    = t >> 2;
    const int g    = t & 3;

    const float* row = out3 + (size_t)blockIdx.x * N_OUT;
    const unsigned FULL = 0xffffffffu;

    float rH[32];
    {
        const float4* base = (const float4*)(row + HOFF + r * 64 + 32 * h);
        #pragma unroll
        for (int k4 = 0; k4 < 8; ++k4) {
            float4 v = base[k4];
            rH[4*k4+0] = v.x; rH[4*k4+1] = v.y; rH[4*k4+2] = v.z; rH[4*k4+3] = v.w;
            sH[r * 65 + 32 * h + 4 * k4 + 0] = v.x;
            sH[r * 65 + 32 * h + 4 * k4 + 1] = v.y;
            sH[r * 65 + 32 * h + 4 * k4 + 2] = v.z;
            sH[r * 65 + 32 * h + 4 * k4 + 3] = v.w;
        }
    }
    if (t < 64)  sq[t] = row[N_P + t];
    if (t < 128) sb[t] = row[HOFF + N_HMAT + t];
    if (t < 64)  sv[t] = 0.125f;
    __syncthreads();

    for (int pit = 0; pit < 10; ++pit) {
        {
            const float4* x4 = (const float4*)(sv + 32 * h);
            float a0=0.f,a1=0.f,a2=0.f,a3=0.f;
            #pragma unroll
            for (int k4 = 0; k4 < 8; ++k4) {
                float4 xv = x4[k4];
                a0 = fmaf(rH[4*k4+0], xv.x, a0);
                a1 = fmaf(rH[4*k4+1], xv.y, a1);
                a2 = fmaf(rH[4*k4+2], xv.z, a2);
                a3 = fmaf(rH[4*k4+3], xv.w, a3);
            }
            float s = (a0 + a1) + (a2 + a3);
            s += __shfl_xor_sync(FULL, s, 1);
            if (h == 0) sw[r] = s;
        }
        __syncthreads();
        {
            float a0=0.f,a1=0.f,a2=0.f,a3=0.f;
            #pragma unroll
            for (int j0 = 0; j0 < 32; j0 += 4) {
                int jj0 = (j0 + 0 + 8 * g) & 31;
                int jj1 = (j0 + 1 + 8 * g) & 31;
                int jj2 = (j0 + 2 + 8 * g) & 31;
                int jj3 = (j0 + 3 + 8 * g) & 31;
                a0 = fmaf(sH[(32*g + jj0) * 65 + c], sw[32*g + jj0], a0);
                a1 = fmaf(sH[(32*g + jj1) * 65 + c], sw[32*g + jj1], a1);
                a2 = fmaf(sH[(32*g + jj2) * 65 + c], sw[32*g + jj2], a2);
                a3 = fmaf(sH[(32*g + jj3) * 65 + c], sw[32*g + jj3], a3);
            }
            float p = (a0 + a1) + (a2 + a3);
            p += __shfl_xor_sync(FULL, p, 1);
            p += __shfl_xor_sync(FULL, p, 2);
            float pp = (g == 0) ? p * p : 0.f;
            #pragma unroll
            for (int off = 16; off >= 1; off >>= 1)
                pp += __shfl_xor_sync(FULL, pp, off);
            if (lane == 0) spart[warp] = pp;
            __syncthreads();
            if (t == 0) {
                float sm = 0.f;
                #pragma unroll
                for (int i = 0; i < 8; ++i) sm += spart[i];
                s_scal = sqrtf(sm) + 1e-12f;
            }
            __syncthreads();
            if (g == 0) sv[c] = p / s_scal;
        }
        __syncthreads();
    }

    {
        const float4* x4 = (const float4*)(sv + 32 * h);
        float a0=0.f,a1=0.f,a2=0.f,a3=0.f;
        #pragma unroll
        for (int k4 = 0; k4 < 8; ++k4) {
            float4 xv = x4[k4];
            a0 = fmaf(rH[4*k4+0], xv.x, a0);
            a1 = fmaf(rH[4*k4+1], xv.y, a1);
            a2 = fmaf(rH[4*k4+2], xv.z, a2);
            a3 = fmaf(rH[4*k4+3], xv.w, a3);
        }
        float s = (a0 + a1) + (a2 + a3);
        s += __shfl_xor_sync(FULL, s, 1);
        float pp = (h == 0) ? s * s : 0.f;
        #pragma unroll
        for (int off = 16; off >= 1; off >>= 1)
            pp += __shfl_xor_sync(FULL, pp, off);
        if (lane == 0) spart[warp] = pp;
        __syncthreads();
        if (t == 0) {
            float sm = 0.f;
            #pragma unroll
            for (int i = 0; i < 8; ++i) sm += spart[i];
            s_tau = 0.9f / (sqrtf(sm) + 1e-6f);
        }
    }

    for (int idx = t; idx < 64 * 65; idx += 256) sQ[idx] = 0.f;
    __syncthreads();
    for (int idx = t; idx < N_P; idx += 256) {
        float p = row[idx];
        int rr = (int)((sqrtf(8.f * (float)idx + 1.f) - 1.f) * 0.5f);
        while ((rr * (rr + 1)) / 2 > idx) --rr;
        while (((rr + 1) * (rr + 2)) / 2 <= idx) ++rr;
        int cc = idx - (rr * (rr + 1)) / 2;
        float val;
        if (cc == rr) {
            float sp = fmaxf(p, 0.f) + log1pf(expf(-fabsf(p)));
            val = 0.1f + sp;
        } else {
            val = p;
        }
        sQ[rr * 65 + cc] = val;
    }
    __syncthreads();
    const float tau = s_tau;
    const float sig = tau;

    float rM[16];
    #pragma unroll
    for (int j = 0; j < 16; ++j) rM[j] = 0.f;
    for (int k = 0; k < 64; ++k) {
        float a = sQ[c * 65 + k];
        #pragma unroll
        for (int j = 0; j < 16; ++j)
            rM[j] = fmaf(a, sQ[(16 * g + j) * 65 + k], rM[j]);
    }
    #pragma unroll
    for (int j = 0; j < 16; ++j) {
        int col = 16 * g + j;
        rM[j] = tau * rM[j] + ((col == c) ? 1.f : 0.f);
    }
    __syncthreads();

    for (int k = 0; k < 64; ++k) {
        const int kc = k >> 4, kj = k & 15;
        float* buf = spiv + (k & 1) * 64;
        float praw = __shfl_sync(FULL, sel16(rM, kj), (lane & ~3) | kc);
        if (c == k) {
            float pinv = 1.f / praw;
            #pragma unroll
            for (int j = 0; j < 16; ++j) {
                bool isk = (g == kc) && (j == kj);
                rM[j] = isk ? pinv : rM[j] * pinv;
            }
            *(float4*)&buf[16*g +  0] = make_float4(rM[0],  rM[1],  rM[2],  rM[3]);
            *(float4*)&buf[16*g +  4] = make_float4(rM[4],  rM[5],  rM[6],  rM[7]);
            *(float4*)&buf[16*g +  8] = make_float4(rM[8],  rM[9],  rM[10], rM[11]);
            *(float4*)&buf[16*g + 12] = make_float4(rM[12], rM[13], rM[14], rM[15]);
        }
        __syncthreads();
        if (c != k) {
            const float f = praw;
            float4 p0 = *(const float4*)&buf[16*g +  0];
            float4 p1 = *(const float4*)&buf[16*g +  4];
            float4 p2 = *(const float4*)&buf[16*g +  8];
            float4 p3 = *(const float4*)&buf[16*g + 12];
            float pv[16] = {p0.x,p0.y,p0.z,p0.w, p1.x,p1.y,p1.z,p1.w,
                            p2.x,p2.y,p2.z,p2.w, p3.x,p3.y,p3.z,p3.w};
            #pragma unroll
            for (int j = 0; j < 16; ++j) {
                bool isk = (g == kc) && (j == kj);
                float upd = fmaf(-f, pv[j], rM[j]);
                rM[j] = isk ? (-f * pv[j]) : upd;
            }
        }
    }
    __syncthreads();

    if (t < 64)  { sxbar[t] = 0.f; st[t] = 0.f; }
    if (t < 128) slam[t] = 0.f;
    float xp = 0.f;
    __syncthreads();

    for (int it = 0; it < QP_ITER; ++it) {
        {
            const float4* x4 = (const float4*)(sxbar + 32 * h);
            float a0=0.f,a1=0.f,a2=0.f,a3=0.f;
            #pragma unroll
            for (int k4 = 0; k4 < 8; ++k4) {
                float4 xv = x4[k4];
                a0 = fmaf(rH[4*k4+0], xv.x, a0);
                a1 = fmaf(rH[4*k4+1], xv.y, a1);
                a2 = fmaf(rH[4*k4+2], xv.z, a2);
                a3 = fmaf(rH[4*k4+3], xv.w, a3);
            }
            float s = (a0 + a1) + (a2 + a3);
            s += __shfl_xor_sync(FULL, s, 1);
            if (h == 0) slam[r] = fmaxf(0.f, slam[r] - sig * (s + sb[r]));
        }
        __syncthreads();
        {
            float a0=0.f,a1=0.f,a2=0.f,a3=0.f;
            #pragma unroll
            for (int j0 = 0; j0 < 32; j0 += 4) {
                int jj0 = (j0 + 0 + 8 * g) & 31;
                int jj1 = (j0 + 1 + 8 * g) & 31;
                int jj2 = (j0 + 2 + 8 * g) & 31;
                int jj3 = (j0 + 3 + 8 * g) & 31;
                a0 = fmaf(sH[(32*g + jj0) * 65 + c], slam[32*g + jj0], a0);
                a1 = fmaf(sH[(32*g + jj1) * 65 + c], slam[32*g + jj1], a1);
                a2 = fmaf(sH[(32*g + jj2) * 65 + c], slam[32*g + jj2], a2);
                a3 = fmaf(sH[(32*g + jj3) * 65 + c], slam[32*g + jj3], a3);
            }
            float p = (a0 + a1) + (a2 + a3);
            p += __shfl_xor_sync(FULL, p, 1);
            p += __shfl_xor_sync(FULL, p, 2);
            if (g == 0) st[c] = xp + tau * (p - sq[c]);
        }
        __syncthreads();
        {
            const float4* t4 = (const float4*)(st + 16 * g);
            float4 t0 = t4[0], t1 = t4[1], t2 = t4[2], t3 = t4[3];
            float a0=0.f,a1=0.f,a2=0.f,a3=0.f;
            a0 = fmaf(rM[0],  t0.x, a0); a1 = fmaf(rM[1],  t0.y, a1);
            a2 = fmaf(rM[2],  t0.z, a2); a3 = fmaf(rM[3],  t0.w, a3);
            a0 = fmaf(rM[4],  t1.x, a0); a1 = fmaf(rM[5],  t1.y, a1);
            a2 = fmaf(rM[6],  t1.z, a2); a3 = fmaf(rM[7],  t1.w, a3);
            a0 = fmaf(rM[8],  t2.x, a0); a1 = fmaf(rM[9],  t2.y, a1);
            a2 = fmaf(rM[10], t2.z, a2); a3 = fmaf(rM[11], t2.w, a3);
            a0 = fmaf(rM[12], t3.x, a0); a1 = fmaf(rM[13], t3.y, a1);
            a2 = fmaf(rM[14], t3.z, a2); a3 = fmaf(rM[15], t3.w, a3);
            float p = (a0 + a1) + (a2 + a3);
            p += __shfl_xor_sync(FULL, p, 1);
            p += __shfl_xor_sync(FULL, p, 2);
            if (g == 0) {
                sxbar[c] = 2.f * p - xp;
                xp = p;
            }
        }
        __syncthreads();
    }

    if (g == 0) xs[(size_t)blockIdx.x * N_QP + c] = xp;
}

// ---------------------------------------------------------------------------
// Launch
// ---------------------------------------------------------------------------
extern "C" void kernel_launch(void* const* d_in, const int* in_sizes, int n_in,
                              void* d_out, int out_size)
{
    const float* x  = (const float*)d_in[0];
    const float* W1 = (const float*)d_in[1];
    const float* b1 = (const float*)d_in[2];
    const float* W2 = (const float*)d_in[3];
    const float* b2 = (const float*)d_in[4];
    const float* W3 = (const float*)d_in[5];
    const float* b3 = (const float*)d_in[6];
    float* out = (float*)d_out;

    float *p_h1, *p_h2, *p_out3;
    __nv_bfloat16 *p_ahi, *p_alo, *p_bhi, *p_blo;
    cudaGetSymbolAddress((void**)&p_h1, g_h1);
    cudaGetSymbolAddress((void**)&p_h2, g_h2);
    cudaGetSymbolAddress((void**)&p_out3, g_out3);
    cudaGetSymbolAddress((void**)&p_ahi, g_a_hi);
    cudaGetSymbolAddress((void**)&p_alo, g_a_lo);
    cudaGetSymbolAddress((void**)&p_bhi, g_b_hi);
    cudaGetSymbolAddress((void**)&p_blo, g_b_lo);

    {
        dim3 grid(HIDDEN / 64, BATCH / 64);
        sgemm_bias<true><<<grid, 256>>>(x, W1, b1, p_h1, BATCH, HIDDEN, INPUT_SIZE);
    }
    {
        dim3 grid(HIDDEN / 64, BATCH / 64);
        sgemm_bias<true><<<grid, 256>>>(p_h1, W2, b2, p_h2, BATCH, HIDDEN, HIDDEN);
    }
    // Split W3 (can overlap with GEMM1/2 on the same stream order; cheap)
    {
        int n4 = (HIDDEN * N_OUT) / 4;
        split_kernel<<<(n4 + 255) / 256, 256>>>(W3, p_bhi, p_blo, n4);
    }
    // Split h2
    {
        int n4 = (BATCH * HIDDEN) / 4;
        split_kernel<<<(n4 + 255) / 256, 256>>>(p_h2, p_ahi, p_alo, n4);
    }
    {
        cudaFuncSetAttribute(gemm3_bf16,
                             cudaFuncAttributeMaxDynamicSharedMemorySize,
                             G3_SMEM_BYTES);
        dim3 grid(G3_N / 96, BATCH / 128);   // 109 x 8
        gemm3_bf16<<<grid, 256, G3_SMEM_BYTES>>>(p_ahi, p_alo, p_bhi, p_blo, b3, p_out3);
    }
    {
        const size_t smem_bytes = (size_t)SOLVER_SMEM_FLOATS * sizeof(float);
        cudaFuncSetAttribute(solver_kernel,
                             cudaFuncAttributeMaxDynamicSharedMemorySize,
                             (int)smem_bytes);
        solver_kernel<<<BATCH, 256, smem_bytes>>>(p_out3, out);
    }
}